// round 15
// baseline (speedup 1.0000x reference)
#include <cuda_runtime.h>
#include <float.h>

// fm [B=4, C=256, H=50, W=50] f32, rois [R=300,5] f32 -> out [R,256,7,7] f32.
#define PH 7
#define PW 7
#define B_ 4
#define C_ 256
#define H_ 50
#define W_ 50
#define HW (H_ * W_)
#define C4 (C_ / 4)                    // row length in float4 units

// channels-last scratch: fmT[b][y][x][c]  (10.24 MB)
__device__ float g_fmT[B_ * HW * C_];

__device__ __forceinline__ int clampi(int v, int lo, int hi) {
    return min(max(v, lo), hi);
}

// [256, 2500] -> [2500, 256] transpose per batch, 32c x 64hw tiles. (validated)
__global__ __launch_bounds__(256) void transpose_kernel(
        const float* __restrict__ in) {
    __shared__ float tile[32][65];
    const int b   = blockIdx.z;
    const int hw0 = blockIdx.x * 64;
    const int c0  = blockIdx.y * 32;
    const int tx  = threadIdx.x;          // 32
    const int ty  = threadIdx.y;          // 8

    #pragma unroll
    for (int j = 0; j < 4; ++j) {
        const int cl = ty + j * 8;
        const float* src = in + (size_t)(b * C_ + c0 + cl) * HW;
        int hw = hw0 + tx;
        if (hw < HW)      tile[cl][tx]      = src[hw];
        hw = hw0 + 32 + tx;
        if (hw < HW)      tile[cl][tx + 32] = src[hw];
    }
    __syncthreads();
    #pragma unroll
    for (int j = 0; j < 8; ++j) {
        const int hwl = ty + j * 8;
        const int hw  = hw0 + hwl;
        if (hw < HW)
            g_fmT[(size_t)(b * HW + hw) * C_ + c0 + tx] = tile[tx][hwl];
    }
}

__device__ __forceinline__ void fold4(float4& acc, float4 a) {
    acc.x = fmaxf(acc.x, a.x);
    acc.y = fmaxf(acc.y, a.y);
    acc.z = fmaxf(acc.z, a.z);
    acc.w = fmaxf(acc.w, a.w);
}

// Branch-free bin max with NC clamped-duplicate columns in flight.
template <int NC>
__device__ __forceinline__ float4 pool_bin(const float4* base, int sh, int bw) {
    int off[NC];
    #pragma unroll
    for (int j = 0; j < NC; ++j)
        off[j] = min(j, bw - 1) * C4;
    float4 acc = make_float4(-FLT_MAX, -FLT_MAX, -FLT_MAX, -FLT_MAX);
    for (int y = 0; y < sh; ++y, base += W_ * C4) {
        #pragma unroll
        for (int j = 0; j < NC; ++j) {
            float4 a = __ldg(base + off[j]);
            fold4(acc, a);
        }
    }
    return acc;
}

// bw in 5..8: two sequential 4-load batches (<=4 loads live at once).
__device__ __forceinline__ float4 pool_bin8(const float4* base, int sh, int bw) {
    int off[8];
    #pragma unroll
    for (int j = 0; j < 8; ++j)
        off[j] = min(j, bw - 1) * C4;
    float4 acc = make_float4(-FLT_MAX, -FLT_MAX, -FLT_MAX, -FLT_MAX);
    for (int y = 0; y < sh; ++y, base += W_ * C4) {
        {
            float4 a0 = __ldg(base + off[0]);
            float4 a1 = __ldg(base + off[1]);
            float4 a2 = __ldg(base + off[2]);
            float4 a3 = __ldg(base + off[3]);
            fold4(acc, a0); fold4(acc, a1); fold4(acc, a2); fold4(acc, a3);
        }
        {
            float4 a0 = __ldg(base + off[4]);
            float4 a1 = __ldg(base + off[5]);
            float4 a2 = __ldg(base + off[6]);
            float4 a3 = __ldg(base + off[7]);
            fold4(acc, a0); fold4(acc, a1); fold4(acc, a2); fold4(acc, a3);
        }
    }
    return acc;
}

// Block = (ph, roi, 128-channel half). Warp = pw bin, lane = float4 quad
// (warp-load = 128 consecutive channels = 512B dense).
__global__ __launch_bounds__(224, 7) void roi_pool_kernel(
        const float* __restrict__ rois, float* __restrict__ out) {
    __shared__ float so[128 * PW];         // [c_local*7 + pw], 3.5 KB

    const int ph   = blockIdx.x;
    const int r    = blockIdx.y;
    const int half = blockIdx.z;           // 0..1 (128 channels each)
    const int lane = threadIdx.x & 31;
    const int pw   = threadIdx.x >> 5;     // 0..6

    // ---- ROI box (block-uniform; jnp.round == rintf under RN) ----
    const float* rp = rois + r * 5;
    const int b  = (int)__ldg(rp + 4);                 // float truncation
    int x0 = clampi((int)rintf(__ldg(rp + 0)), 0, W_ - 1);
    int x1 = clampi((int)rintf(__ldg(rp + 2)), 0, W_ - 1);
    int y0 = clampi((int)rintf(__ldg(rp + 1)), 0, H_ - 1);
    int y1 = clampi((int)rintf(__ldg(rp + 3)), 0, H_ - 1);
    x1 = max(x1, x0 + 1);                  // edges may reach 50; reads <= 49
    y1 = max(y1, y0 + 1);
    const int w = x1 - x0;                 // 1..49
    const int h = y1 - y0;

    const int hs = y0 + (ph * h) / PH;
    const int sh = y0 + ((ph + 1) * h + PH - 1) / PH - hs;   // 1..8
    const int ws = x0 + (pw * w) / PW;
    const int bw = x0 + ((pw + 1) * w + PW - 1) / PW - ws;   // 1..8

    const float4* base = (const float4*)g_fmT
        + ((size_t)b * HW + hs * W_ + ws) * C4 + half * 32 + lane;

    float4 acc;
    if (bw == 1)      acc = pool_bin<1>(base, sh, bw);
    else if (bw == 2) acc = pool_bin<2>(base, sh, bw);
    else if (bw == 3) acc = pool_bin<3>(base, sh, bw);
    else if (bw == 4) acc = pool_bin<4>(base, sh, bw);
    else              acc = pool_bin8(base, sh, bw);

    so[(4 * lane + 0) * PW + pw] = acc.x;
    so[(4 * lane + 1) * PW + pw] = acc.y;
    so[(4 * lane + 2) * PW + pw] = acc.z;
    so[(4 * lane + 3) * PW + pw] = acc.w;
    __syncthreads();

    // out[r][half*128 + c_local][ph][pw]; 896 floats, 4 per thread
    float* ob = out + ((size_t)r * C_ + half * 128) * (PH * PW) + ph * PW;
    #pragma unroll
    for (int i = threadIdx.x; i < 128 * PW; i += 224) {
        int c  = i / PW;
        int pp = i - c * PW;
        ob[c * (PH * PW) + pp] = so[i];
    }
}

extern "C" void kernel_launch(void* const* d_in, const int* in_sizes, int n_in,
                              void* d_out, int out_size) {
    const float* fm   = (const float*)d_in[0];
    const float* rois = (const float*)d_in[1];
    float* out = (float*)d_out;

    int R = in_sizes[1] / 5;               // 300

    dim3 tgrid((HW + 63) / 64, C_ / 32, B_);   // 40 x 8 x 4
    transpose_kernel<<<tgrid, dim3(32, 8)>>>(fm);

    dim3 pgrid(PH, R, 2);                  // 7 x 300 x 2
    roi_pool_kernel<<<pgrid, 224>>>(rois, out);
}

// round 16
// speedup vs baseline: 1.1486x; 1.1486x over previous
#include <cuda_runtime.h>
#include <float.h>

// fm [B=4, C=256, H=50, W=50] f32, rois [R=300,5] f32 -> out [R,256,7,7] f32.
#define PH 7
#define PW 7
#define B_ 4
#define C_ 256
#define H_ 50
#define W_ 50
#define HW (H_ * W_)
#define C4 (C_ / 4)                    // row length in float4 units

// channels-last scratch: fmT[b][y][x][c]  (10.24 MB)
__device__ float g_fmT[B_ * HW * C_];

__device__ __forceinline__ int clampi(int v, int lo, int hi) {
    return min(max(v, lo), hi);
}

// [256, 2500] -> [2500, 256] transpose per batch, 32c x 64hw tiles. (validated)
__global__ __launch_bounds__(256) void transpose_kernel(
        const float* __restrict__ in) {
    __shared__ float tile[32][65];
    const int b   = blockIdx.z;
    const int hw0 = blockIdx.x * 64;
    const int c0  = blockIdx.y * 32;
    const int tx  = threadIdx.x;          // 32
    const int ty  = threadIdx.y;          // 8

    #pragma unroll
    for (int j = 0; j < 4; ++j) {
        const int cl = ty + j * 8;
        const float* src = in + (size_t)(b * C_ + c0 + cl) * HW;
        int hw = hw0 + tx;
        if (hw < HW)      tile[cl][tx]      = src[hw];
        hw = hw0 + 32 + tx;
        if (hw < HW)      tile[cl][tx + 32] = src[hw];
    }
    __syncthreads();
    #pragma unroll
    for (int j = 0; j < 8; ++j) {
        const int hwl = ty + j * 8;
        const int hw  = hw0 + hwl;
        if (hw < HW)
            g_fmT[(size_t)(b * HW + hw) * C_ + c0 + tx] = tile[tx][hwl];
    }
}

__device__ __forceinline__ void fold4(float4& acc, float4 a) {
    acc.x = fmaxf(acc.x, a.x);
    acc.y = fmaxf(acc.y, a.y);
    acc.z = fmaxf(acc.z, a.z);
    acc.w = fmaxf(acc.w, a.w);
}

// Branch-free bin max with NC clamped-duplicate columns in flight (NC<=4).
template <int NC>
__device__ __forceinline__ float4 pool_bin(const float4* base, int sh, int bw) {
    int off[NC];
    #pragma unroll
    for (int j = 0; j < NC; ++j)
        off[j] = min(j, bw - 1) * C4;
    float4 acc = make_float4(-FLT_MAX, -FLT_MAX, -FLT_MAX, -FLT_MAX);
    for (int y = 0; y < sh; ++y, base += W_ * C4) {
        #pragma unroll
        for (int j = 0; j < NC; ++j) {
            float4 a = __ldg(base + off[j]);
            fold4(acc, a);
        }
    }
    return acc;
}

// bw in 5..8: two sequential 4-load batches; batch-2 offsets computed
// in-batch to keep their live ranges short (<=4 float4 loads live).
__device__ __forceinline__ float4 pool_bin8(const float4* base, int sh, int bw) {
    const int o4 = min(4, bw - 1) * C4;
    const int o5 = min(5, bw - 1) * C4;
    const int o6 = min(6, bw - 1) * C4;
    const int o7 = (bw - 1) * C4;
    float4 acc = make_float4(-FLT_MAX, -FLT_MAX, -FLT_MAX, -FLT_MAX);
    for (int y = 0; y < sh; ++y, base += W_ * C4) {
        {
            float4 a0 = __ldg(base);
            float4 a1 = __ldg(base + C4);
            float4 a2 = __ldg(base + 2 * C4);
            float4 a3 = __ldg(base + 3 * C4);
            fold4(acc, a0); fold4(acc, a1); fold4(acc, a2); fold4(acc, a3);
        }
        {
            float4 a0 = __ldg(base + o4);
            float4 a1 = __ldg(base + o5);
            float4 a2 = __ldg(base + o6);
            float4 a3 = __ldg(base + o7);
            fold4(acc, a0); fold4(acc, a1); fold4(acc, a2); fold4(acc, a3);
        }
    }
    return acc;
}

// Block = (ph, roi, 128-channel half). Warp = pw bin, lane = float4 quad
// (warp-load = 128 consecutive channels = 512B dense).
__global__ __launch_bounds__(224, 6) void roi_pool_kernel(
        const float* __restrict__ rois, float* __restrict__ out) {
    __shared__ float so[128 * PW];         // [c_local*7 + pw], 3.5 KB

    const int ph   = blockIdx.x;
    const int r    = blockIdx.y;
    const int half = blockIdx.z;           // 0..1 (128 channels each)
    const int lane = threadIdx.x & 31;
    const int pw   = threadIdx.x >> 5;     // 0..6

    // ---- ROI box (block-uniform; jnp.round == rintf under RN) ----
    const float* rp = rois + r * 5;
    const int b  = (int)__ldg(rp + 4);                 // float truncation
    int x0 = clampi((int)rintf(__ldg(rp + 0)), 0, W_ - 1);
    int x1 = clampi((int)rintf(__ldg(rp + 2)), 0, W_ - 1);
    int y0 = clampi((int)rintf(__ldg(rp + 1)), 0, H_ - 1);
    int y1 = clampi((int)rintf(__ldg(rp + 3)), 0, H_ - 1);
    x1 = max(x1, x0 + 1);                  // edges may reach 50; reads <= 49
    y1 = max(y1, y0 + 1);
    const int w = x1 - x0;                 // 1..49
    const int h = y1 - y0;

    const int hs = y0 + (ph * h) / PH;
    const int sh = y0 + ((ph + 1) * h + PH - 1) / PH - hs;   // 1..8
    const int ws = x0 + (pw * w) / PW;
    const int bw = x0 + ((pw + 1) * w + PW - 1) / PW - ws;   // 1..8

    const float4* base = (const float4*)g_fmT
        + ((size_t)b * HW + hs * W_ + ws) * C4 + half * 32 + lane;

    float4 acc;
    if (bw == 1)      acc = pool_bin<1>(base, sh, bw);
    else if (bw == 2) acc = pool_bin<2>(base, sh, bw);
    else if (bw == 3) acc = pool_bin<3>(base, sh, bw);
    else if (bw == 4) acc = pool_bin<4>(base, sh, bw);
    else              acc = pool_bin8(base, sh, bw);

    so[(4 * lane + 0) * PW + pw] = acc.x;
    so[(4 * lane + 1) * PW + pw] = acc.y;
    so[(4 * lane + 2) * PW + pw] = acc.z;
    so[(4 * lane + 3) * PW + pw] = acc.w;
    __syncthreads();

    // out[r][half*128 + c_local][ph][pw]; 896 floats, 4 per thread
    float* ob = out + ((size_t)r * C_ + half * 128) * (PH * PW) + ph * PW;
    #pragma unroll
    for (int i = threadIdx.x; i < 128 * PW; i += 224) {
        int c  = i / PW;
        int pp = i - c * PW;
        ob[c * (PH * PW) + pp] = so[i];
    }
}

extern "C" void kernel_launch(void* const* d_in, const int* in_sizes, int n_in,
                              void* d_out, int out_size) {
    const float* fm   = (const float*)d_in[0];
    const float* rois = (const float*)d_in[1];
    float* out = (float*)d_out;

    int R = in_sizes[1] / 5;               // 300

    dim3 tgrid((HW + 63) / 64, C_ / 32, B_);   // 40 x 8 x 4
    transpose_kernel<<<tgrid, dim3(32, 8)>>>(fm);

    dim3 pgrid(PH, R, 2);                  // 7 x 300 x 2
    roi_pool_kernel<<<pgrid, 224>>>(rois, out);
}

// round 17
// speedup vs baseline: 1.2161x; 1.0588x over previous
#include <cuda_runtime.h>
#include <float.h>

// fm [B=4, C=256, H=50, W=50] f32, rois [R=300,5] f32 -> out [R,256,7,7] f32.
#define PH 7
#define PW 7
#define B_ 4
#define C_ 256
#define H_ 50
#define W_ 50
#define HW (H_ * W_)
#define C4 (C_ / 4)                    // row length in float4 units

// channels-last scratch: fmT[b][y][x][c]  (10.24 MB)
__device__ float g_fmT[B_ * HW * C_];

__device__ __forceinline__ int clampi(int v, int lo, int hi) {
    return min(max(v, lo), hi);
}

// [256, 2500] -> [2500, 256] transpose per batch, 32c x 64hw tiles. (validated)
__global__ __launch_bounds__(256) void transpose_kernel(
        const float* __restrict__ in) {
    __shared__ float tile[32][65];
    const int b   = blockIdx.z;
    const int hw0 = blockIdx.x * 64;
    const int c0  = blockIdx.y * 32;
    const int tx  = threadIdx.x;          // 32
    const int ty  = threadIdx.y;          // 8

    #pragma unroll
    for (int j = 0; j < 4; ++j) {
        const int cl = ty + j * 8;
        const float* src = in + (size_t)(b * C_ + c0 + cl) * HW;
        int hw = hw0 + tx;
        if (hw < HW)      tile[cl][tx]      = src[hw];
        hw = hw0 + 32 + tx;
        if (hw < HW)      tile[cl][tx + 32] = src[hw];
    }
    __syncthreads();
    #pragma unroll
    for (int j = 0; j < 8; ++j) {
        const int hwl = ty + j * 8;
        const int hw  = hw0 + hwl;
        if (hw < HW)
            g_fmT[(size_t)(b * HW + hw) * C_ + c0 + tx] = tile[tx][hwl];
    }
}

__device__ __forceinline__ void fold4(float4& acc, float4 a) {
    acc.x = fmaxf(acc.x, a.x);
    acc.y = fmaxf(acc.y, a.y);
    acc.z = fmaxf(acc.z, a.z);
    acc.w = fmaxf(acc.w, a.w);
}

// Software-pipelined bin max (NC <= 4): next row's loads issue before the
// current row's folds -> steady-state 2*NC loads in flight, one latency
// exposure per bin instead of sh.
template <int NC>
__device__ __forceinline__ float4 pool_bin(const float4* base, int sh, int bw) {
    int off[NC];
    #pragma unroll
    for (int j = 0; j < NC; ++j)
        off[j] = min(j, bw - 1) * C4;

    float4 acc = make_float4(-FLT_MAX, -FLT_MAX, -FLT_MAX, -FLT_MAX);
    float4 cur[NC];
    #pragma unroll
    for (int j = 0; j < NC; ++j)
        cur[j] = __ldg(base + off[j]);

    for (int y = 1; y < sh; ++y) {
        base += W_ * C4;
        float4 nxt[NC];
        #pragma unroll
        for (int j = 0; j < NC; ++j)
            nxt[j] = __ldg(base + off[j]);     // issue before folding cur
        #pragma unroll
        for (int j = 0; j < NC; ++j)
            fold4(acc, cur[j]);
        #pragma unroll
        for (int j = 0; j < NC; ++j)
            cur[j] = nxt[j];                   // register rename
    }
    #pragma unroll
    for (int j = 0; j < NC; ++j)
        fold4(acc, cur[j]);
    return acc;
}

// bw in 5..8: two 4-load batches per row (8 loads in flight per row).
__device__ __forceinline__ float4 pool_bin8(const float4* base, int sh, int bw) {
    const int o4 = min(4, bw - 1) * C4;
    const int o5 = min(5, bw - 1) * C4;
    const int o6 = min(6, bw - 1) * C4;
    const int o7 = (bw - 1) * C4;
    float4 acc = make_float4(-FLT_MAX, -FLT_MAX, -FLT_MAX, -FLT_MAX);
    for (int y = 0; y < sh; ++y, base += W_ * C4) {
        float4 a0 = __ldg(base);
        float4 a1 = __ldg(base + C4);
        float4 a2 = __ldg(base + 2 * C4);
        float4 a3 = __ldg(base + 3 * C4);
        float4 a4 = __ldg(base + o4);
        float4 a5 = __ldg(base + o5);
        float4 a6 = __ldg(base + o6);
        float4 a7 = __ldg(base + o7);
        fold4(acc, a0); fold4(acc, a1); fold4(acc, a2); fold4(acc, a3);
        fold4(acc, a4); fold4(acc, a5); fold4(acc, a6); fold4(acc, a7);
    }
    return acc;
}

// Block = (ph, roi, 128-channel half). Warp = pw bin, lane = float4 quad
// (warp-load = 128 consecutive channels = 512B dense).
__global__ __launch_bounds__(224) void roi_pool_kernel(
        const float* __restrict__ rois, float* __restrict__ out) {
    __shared__ float so[128 * PW];         // [c_local*7 + pw], 3.5 KB

    const int ph   = blockIdx.x;
    const int r    = blockIdx.y;
    const int half = blockIdx.z;           // 0..1 (128 channels each)
    const int lane = threadIdx.x & 31;
    const int pw   = threadIdx.x >> 5;     // 0..6

    // ---- ROI box (block-uniform; jnp.round == rintf under RN) ----
    const float* rp = rois + r * 5;
    const int b  = (int)__ldg(rp + 4);                 // float truncation
    int x0 = clampi((int)rintf(__ldg(rp + 0)), 0, W_ - 1);
    int x1 = clampi((int)rintf(__ldg(rp + 2)), 0, W_ - 1);
    int y0 = clampi((int)rintf(__ldg(rp + 1)), 0, H_ - 1);
    int y1 = clampi((int)rintf(__ldg(rp + 3)), 0, H_ - 1);
    x1 = max(x1, x0 + 1);                  // edges may reach 50; reads <= 49
    y1 = max(y1, y0 + 1);
    const int w = x1 - x0;                 // 1..49
    const int h = y1 - y0;

    const int hs = y0 + (ph * h) / PH;
    const int sh = y0 + ((ph + 1) * h + PH - 1) / PH - hs;   // 1..8
    const int ws = x0 + (pw * w) / PW;
    const int bw = x0 + ((pw + 1) * w + PW - 1) / PW - ws;   // 1..8

    const float4* base = (const float4*)g_fmT
        + ((size_t)b * HW + hs * W_ + ws) * C4 + half * 32 + lane;

    float4 acc;
    if (bw == 1)      acc = pool_bin<1>(base, sh, bw);
    else if (bw == 2) acc = pool_bin<2>(base, sh, bw);
    else if (bw == 3) acc = pool_bin<3>(base, sh, bw);
    else if (bw == 4) acc = pool_bin<4>(base, sh, bw);
    else              acc = pool_bin8(base, sh, bw);

    so[(4 * lane + 0) * PW + pw] = acc.x;
    so[(4 * lane + 1) * PW + pw] = acc.y;
    so[(4 * lane + 2) * PW + pw] = acc.z;
    so[(4 * lane + 3) * PW + pw] = acc.w;
    __syncthreads();

    // out[r][half*128 + c_local][ph][pw]; 896 floats, 4 per thread
    float* ob = out + ((size_t)r * C_ + half * 128) * (PH * PW) + ph * PW;
    #pragma unroll
    for (int i = threadIdx.x; i < 128 * PW; i += 224) {
        int c  = i / PW;
        int pp = i - c * PW;
        ob[c * (PH * PW) + pp] = so[i];
    }
}

extern "C" void kernel_launch(void* const* d_in, const int* in_sizes, int n_in,
                              void* d_out, int out_size) {
    const float* fm   = (const float*)d_in[0];
    const float* rois = (const float*)d_in[1];
    float* out = (float*)d_out;

    int R = in_sizes[1] / 5;               // 300

    dim3 tgrid((HW + 63) / 64, C_ / 32, B_);   // 40 x 8 x 4
    transpose_kernel<<<tgrid, dim3(32, 8)>>>(fm);

    dim3 pgrid(PH, R, 2);                  // 7 x 300 x 2
    roi_pool_kernel<<<pgrid, 224>>>(rois, out);
}